// round 8
// baseline (speedup 1.0000x reference)
#include <cuda_runtime.h>
#include <cuda_bf16.h>

// Problem constants
#define NN   3072
#define FF   256
#define HH   8
#define DD   128
#define OUTD 64
#define MAXD 384
#define SPLITK 4

// ---------------- device scratch ----------------
__device__ __align__(16) __nv_bfloat16 g_Whb [HH * NN * DD];
__device__ __align__(16) float         g_ha  [HH * NN * DD];
__device__ __align__(16) float         g_hc  [NN * HH * DD];
__device__ __align__(16) float         g_who [SPLITK * NN * OUTD];
__device__ __align__(16) __nv_bfloat16 g_Whob[NN * OUTD];
__device__ __align__(16) float         g_tw  [HH * DD];       // theta @ W0 per head
__device__ float g_f1 [HH * NN];
__device__ float g_f2 [HH * NN];
__device__ float g_f1o[NN];
__device__ float g_f2o[NN];
__device__ int   g_nbr[NN * MAXD];
__device__ int   g_deg[NN];

// ---------------- theta @ W0 precompute (per head) ----------------
__global__ void thetaW_kernel(const float* __restrict__ theta,
                              const float* __restrict__ W0) {
    int h = blockIdx.x;
    int c = threadIdx.x;            // 0..DD-1
    float s = 0.0f;
    const float* Wh = W0 + (long)h * FF * DD + c;
#pragma unroll 4
    for (int k = 0; k < FF; k++) s += theta[k] * Wh[(long)k * DD];
    g_tw[h * DD + c] = s;
}

// ---------------- CSR build (float4) ----------------
__global__ void build_csr_kernel(const float* __restrict__ adj) {
    int i = blockIdx.x;
    __shared__ int cnt;
    if (threadIdx.x == 0) cnt = 0;
    __syncthreads();
    const float4* row = (const float4*)(adj + (long)i * NN);
    for (int q = threadIdx.x; q < NN / 4; q += blockDim.x) {
        float4 v = row[q];
        int j = 4 * q;
        if (v.x > 0.0f) { int p = atomicAdd(&cnt, 1); if (p < MAXD) g_nbr[i * MAXD + p] = j; }
        if (v.y > 0.0f) { int p = atomicAdd(&cnt, 1); if (p < MAXD) g_nbr[i * MAXD + p] = j + 1; }
        if (v.z > 0.0f) { int p = atomicAdd(&cnt, 1); if (p < MAXD) g_nbr[i * MAXD + p] = j + 2; }
        if (v.w > 0.0f) { int p = atomicAdd(&cnt, 1); if (p < MAXD) g_nbr[i * MAXD + p] = j + 3; }
    }
    __syncthreads();
    if (threadIdx.x == 0) g_deg[i] = cnt < MAXD ? cnt : MAXD;
}

// ---------------- mma / cp.async helpers ----------------
__device__ __forceinline__ unsigned f2tf(unsigned bits) {
    unsigned u;
    asm("cvt.rna.tf32.f32 %0, %1;" : "=r"(u) : "r"(bits));
    return u;
}
__device__ __forceinline__ void mma_tf32(float c[4], const unsigned a[4], const unsigned b[2]) {
    asm("mma.sync.aligned.m16n8k8.row.col.f32.tf32.tf32.f32 "
        "{%0,%1,%2,%3}, {%4,%5,%6,%7}, {%8,%9}, {%0,%1,%2,%3};"
        : "+f"(c[0]), "+f"(c[1]), "+f"(c[2]), "+f"(c[3])
        : "r"(a[0]), "r"(a[1]), "r"(a[2]), "r"(a[3]), "r"(b[0]), "r"(b[1]));
}
__device__ __forceinline__ void cpa16(void* smem_dst, const void* gsrc) {
    unsigned saddr = (unsigned)__cvta_generic_to_shared(smem_dst);
    asm volatile("cp.async.ca.shared.global [%0], [%1], 16;" :: "r"(saddr), "l"(gsrc));
}
__device__ __forceinline__ void cpa_commit() { asm volatile("cp.async.commit_group;"); }
template <int N>
__device__ __forceinline__ void cpa_wait() { asm volatile("cp.async.wait_group %0;" :: "n"(N)); }

// ---------------- f32x2 packed helpers (sm_103a FFMA2) ----------------
__device__ __forceinline__ unsigned long long fma2(unsigned long long a,
                                                   unsigned long long b,
                                                   unsigned long long c) {
    unsigned long long d;
    asm("fma.rn.f32x2 %0, %1, %2, %3;" : "=l"(d) : "l"(a), "l"(b), "l"(c));
    return d;
}
// bf16x2 word -> packed f32x2 {lo, hi} (exact)
__device__ __forceinline__ unsigned long long cvt2(unsigned u) {
    unsigned lo = u << 16;
    unsigned hi = u & 0xffff0000u;
    unsigned long long r;
    asm("mov.b64 %0, {%1, %2};" : "=l"(r) : "r"(lo), "r"(hi));
    return r;
}
__device__ __forceinline__ unsigned long long dup2(float f) {
    unsigned b = __float_as_uint(f);
    unsigned long long r;
    asm("mov.b64 %0, {%1, %2};" : "=l"(r) : "r"(b), "r"(b));
    return r;
}
__device__ __forceinline__ float2 unpk(unsigned long long p) {
    unsigned lo, hi;
    asm("mov.b64 {%0, %1}, %2;" : "=r"(lo), "=r"(hi) : "l"(p));
    return make_float2(__uint_as_float(lo), __uint_as_float(hi));
}

// ---------------- pipelined tf32 GEMM + fused epilogue ----------------
template <int BM, int BN, int BK, int WM, int WN, bool FUSE_THETA>
__global__ void mma_gemm(const float* __restrict__ A,
                         const float* __restrict__ B,
                         __nv_bfloat16* __restrict__ Cb,
                         const float* __restrict__ avec,
                         float* __restrict__ f1,
                         float* __restrict__ f2,
                         int M, int Nc, int K,
                         long strideA, long strideB, long strideAv,
                         const int* __restrict__ obs) {
    constexpr int WARPS_N = BN / WN;
    constexpr int WARPS_M = BM / WM;
    constexpr int THREADS = WARPS_M * WARPS_N * 32;
    constexpr int MT = WM / 16, NT = WN / 8;
    constexpr int AP = BK + 4;
    constexpr int BP = BN + 8;
    constexpr int A_OPS = BM * BK / (4 * THREADS);
    constexpr int B_OPS = BK * BN / (4 * THREADS);

    __shared__ unsigned As[2][BM][AP];
    __shared__ unsigned Bs[2][BK][BP];
    __shared__ float f1s[BM], f2s[BM];

    int z = blockIdx.z;
    A    += (long)z * strideA;
    B    += (long)z * strideB;
    avec += (long)z * strideAv;
    Cb   += (long)z * M * Nc;
    f1   += (long)z * M;
    f2   += (long)z * M;

    int tid  = threadIdx.x;
    int brow = blockIdx.y * BM;
    int warp = tid >> 5, lane = tid & 31;
    int gid  = lane >> 2, tig = lane & 3;
    int wm   = (warp / WARPS_N) * WM;
    int wn   = (warp % WARPS_N) * WN;

    if (tid < BM) { f1s[tid] = 0.0f; f2s[tid] = 0.0f; }

    float c[MT][NT][4];
#pragma unroll
    for (int i = 0; i < MT; i++)
#pragma unroll
        for (int j = 0; j < NT; j++)
#pragma unroll
            for (int q = 0; q < 4; q++) c[i][j][q] = 0.0f;

    const int KT = K / BK;
    auto issue = [&](int kt, int s) {
        int k0 = kt * BK;
#pragma unroll
        for (int l = 0; l < A_OPS; l++) {
            int idx = tid + l * THREADS;
            int r  = idx / (BK / 4);
            int c4 = idx % (BK / 4);
            cpa16(&As[s][r][c4 * 4], &A[(long)(brow + r) * K + k0 + c4 * 4]);
        }
#pragma unroll
        for (int l = 0; l < B_OPS; l++) {
            int idx = tid + l * THREADS;
            int r  = idx / (BN / 4);
            int c4 = idx % (BN / 4);
            cpa16(&Bs[s][r][c4 * 4], &B[(long)(k0 + r) * Nc + c4 * 4]);
        }
        cpa_commit();
    };
    auto compute = [&](int s) {
#pragma unroll
        for (int kk = 0; kk < BK; kk += 8) {
            unsigned a[MT][4], b[NT][2];
#pragma unroll
            for (int mt = 0; mt < MT; mt++) {
                int r0 = wm + mt * 16 + gid;
                a[mt][0] = f2tf(As[s][r0][kk + tig]);
                a[mt][1] = f2tf(As[s][r0 + 8][kk + tig]);
                a[mt][2] = f2tf(As[s][r0][kk + tig + 4]);
                a[mt][3] = f2tf(As[s][r0 + 8][kk + tig + 4]);
            }
#pragma unroll
            for (int nt = 0; nt < NT; nt++) {
                int cn = wn + nt * 8 + gid;
                b[nt][0] = f2tf(Bs[s][kk + tig][cn]);
                b[nt][1] = f2tf(Bs[s][kk + tig + 4][cn]);
            }
#pragma unroll
            for (int mt = 0; mt < MT; mt++)
#pragma unroll
                for (int nt = 0; nt < NT; nt++)
                    mma_tf32(c[mt][nt], a[mt], b[nt]);
        }
    };

    issue(0, 0);
    for (int kt = 0; kt < KT; kt++) {
        if (kt + 1 < KT) { issue(kt + 1, (kt + 1) & 1); cpa_wait<1>(); }
        else             { cpa_wait<0>(); }
        __syncthreads();
        compute(kt & 1);
        __syncthreads();
    }

    // ---- epilogue: (+theta) bf16 store + f1/f2 ----
#pragma unroll
    for (int mt = 0; mt < MT; mt++) {
        int rl0 = wm + mt * 16 + gid;
        int rl1 = rl0 + 8;
        bool s0 = false, s1 = false;
        if (FUSE_THETA) {
            s0 = (obs[brow + rl0] == 1);
            s1 = (obs[brow + rl1] == 1);
        }
        float p10 = 0.f, p20 = 0.f, p11 = 0.f, p21 = 0.f;
#pragma unroll
        for (int nt = 0; nt < NT; nt++) {
            int col = wn + nt * 8 + tig * 2;
            float c0 = c[mt][nt][0], c1 = c[mt][nt][1];
            float c2 = c[mt][nt][2], c3 = c[mt][nt][3];
            if (FUSE_THETA) {
                float tw0 = g_tw[z * DD + col], tw1 = g_tw[z * DD + col + 1];
                if (s0) { c0 += tw0; c1 += tw1; }
                if (s1) { c2 += tw0; c3 += tw1; }
            }
            float a0 = __ldg(&avec[col]),      a1 = __ldg(&avec[col + 1]);
            float b0 = __ldg(&avec[Nc + col]), b1 = __ldg(&avec[Nc + col + 1]);
            p10 += c0 * a0 + c1 * a1;
            p20 += c0 * b0 + c1 * b1;
            p11 += c2 * a0 + c3 * a1;
            p21 += c2 * b0 + c3 * b1;
            *(__nv_bfloat162*)&Cb[(long)(brow + rl0) * Nc + col] =
                __float22bfloat162_rn(make_float2(c0, c1));
            *(__nv_bfloat162*)&Cb[(long)(brow + rl1) * Nc + col] =
                __float22bfloat162_rn(make_float2(c2, c3));
        }
#pragma unroll
        for (int o = 2; o; o >>= 1) {
            p10 += __shfl_down_sync(0xffffffffu, p10, o, 4);
            p20 += __shfl_down_sync(0xffffffffu, p20, o, 4);
            p11 += __shfl_down_sync(0xffffffffu, p11, o, 4);
            p21 += __shfl_down_sync(0xffffffffu, p21, o, 4);
        }
        if (tig == 0) {
            atomicAdd(&f1s[rl0], p10);
            atomicAdd(&f2s[rl0], p20);
            atomicAdd(&f1s[rl1], p11);
            atomicAdd(&f2s[rl1], p21);
        }
    }
    __syncthreads();
    if (tid < BM) {
        f1[brow + tid] = f1s[tid];
        f2[brow + tid] = f2s[tid];
    }
}

// ---------------- split-K output GEMM (fp32 partials, no atomics) ----------------
__global__ void mma_splitk(const float* __restrict__ A,
                           const float* __restrict__ B,
                           int M, int Nc, int K) {
    constexpr int BM = 64, BN = 64, BK = 16;
    constexpr int THREADS = 128;
    constexpr int MT = 2, NT = 4;
    constexpr int AP = BK + 4;
    constexpr int BP = BN + 8;
    constexpr int A_OPS = BM * BK / (4 * THREADS);
    constexpr int B_OPS = BK * BN / (4 * THREADS);

    __shared__ unsigned As[2][BM][AP];
    __shared__ unsigned Bs[2][BK][BP];

    int tid  = threadIdx.x;
    int ksp  = blockIdx.x;
    int brow = blockIdx.y * BM;
    int kBeg = ksp * (K / SPLITK);
    int warp = tid >> 5, lane = tid & 31;
    int gid  = lane >> 2, tig = lane & 3;
    int wm   = (warp / 2) * 32;
    int wn   = (warp % 2) * 32;
    float* Cf = g_who + (long)ksp * M * Nc;

    float c[MT][NT][4];
#pragma unroll
    for (int i = 0; i < MT; i++)
#pragma unroll
        for (int j = 0; j < NT; j++)
#pragma unroll
            for (int q = 0; q < 4; q++) c[i][j][q] = 0.0f;

    const int KT = (K / SPLITK) / BK;
    auto issue = [&](int kt, int s) {
        int k0 = kBeg + kt * BK;
#pragma unroll
        for (int l = 0; l < A_OPS; l++) {
            int idx = tid + l * THREADS;
            int r  = idx / (BK / 4);
            int c4 = idx % (BK / 4);
            cpa16(&As[s][r][c4 * 4], &A[(long)(brow + r) * K + k0 + c4 * 4]);
        }
#pragma unroll
        for (int l = 0; l < B_OPS; l++) {
            int idx = tid + l * THREADS;
            int r  = idx / (BN / 4);
            int c4 = idx % (BN / 4);
            cpa16(&Bs[s][r][c4 * 4], &B[(long)(k0 + r) * Nc + c4 * 4]);
        }
        cpa_commit();
    };
    auto compute = [&](int s) {
#pragma unroll
        for (int kk = 0; kk < BK; kk += 8) {
            unsigned a[MT][4], b[NT][2];
#pragma unroll
            for (int mt = 0; mt < MT; mt++) {
                int r0 = wm + mt * 16 + gid;
                a[mt][0] = f2tf(As[s][r0][kk + tig]);
                a[mt][1] = f2tf(As[s][r0 + 8][kk + tig]);
                a[mt][2] = f2tf(As[s][r0][kk + tig + 4]);
                a[mt][3] = f2tf(As[s][r0 + 8][kk + tig + 4]);
            }
#pragma unroll
            for (int nt = 0; nt < NT; nt++) {
                int cn = wn + nt * 8 + gid;
                b[nt][0] = f2tf(Bs[s][kk + tig][cn]);
                b[nt][1] = f2tf(Bs[s][kk + tig + 4][cn]);
            }
#pragma unroll
            for (int mt = 0; mt < MT; mt++)
#pragma unroll
                for (int nt = 0; nt < NT; nt++)
                    mma_tf32(c[mt][nt], a[mt], b[nt]);
        }
    };

    issue(0, 0);
    for (int kt = 0; kt < KT; kt++) {
        if (kt + 1 < KT) { issue(kt + 1, (kt + 1) & 1); cpa_wait<1>(); }
        else             { cpa_wait<0>(); }
        __syncthreads();
        compute(kt & 1);
        __syncthreads();
    }

#pragma unroll
    for (int mt = 0; mt < MT; mt++) {
        int rl0 = brow + wm + mt * 16 + gid;
        int rl1 = rl0 + 8;
#pragma unroll
        for (int nt = 0; nt < NT; nt++) {
            int col = wn + nt * 8 + tig * 2;
            *(float2*)&Cf[(long)rl0 * Nc + col] = make_float2(c[mt][nt][0], c[mt][nt][1]);
            *(float2*)&Cf[(long)rl1 * Nc + col] = make_float2(c[mt][nt][2], c[mt][nt][3]);
        }
    }
}

// ---------------- combine split-K partials + f1o/f2o + bf16 ----------------
__global__ void out_epi(const float* __restrict__ ao) {
    int warp = threadIdx.x >> 5, lane = threadIdx.x & 31;
    int r = blockIdx.x * 8 + warp;
    float v0 = 0.f, v1 = 0.f;
#pragma unroll
    for (int s = 0; s < SPLITK; s++) {
        const float* row = g_who + (long)s * NN * OUTD + (long)r * OUTD;
        v0 += row[lane];
        v1 += row[lane + 32];
    }
    float p1 = v0 * __ldg(&ao[lane]) + v1 * __ldg(&ao[lane + 32]);
    float p2 = v0 * __ldg(&ao[OUTD + lane]) + v1 * __ldg(&ao[OUTD + lane + 32]);
#pragma unroll
    for (int o = 16; o; o >>= 1) {
        p1 += __shfl_xor_sync(0xffffffffu, p1, o);
        p2 += __shfl_xor_sync(0xffffffffu, p2, o);
    }
    if (lane == 0) { g_f1o[r] = p1; g_f2o[r] = p2; }
    g_Whob[r * OUTD + lane]      = __float2bfloat16(v0);
    g_Whob[r * OUTD + lane + 32] = __float2bfloat16(v1);
}

// ---------------- warp-per-(i,h) sparse attention + ELU ----------------
// block = 256 (8 warps). Gather: RPI rows per warp-iteration, LPR lanes per row,
// 8 bf16 feats per lane (LDG.128 covers the whole row). FFMA2 accumulate.
template <int D>
__global__ void attn_warp(const __nv_bfloat16* __restrict__ Whb,
                          const float* __restrict__ f1,
                          const float* __restrict__ f2,
                          float* __restrict__ out,
                          int iStride, int hStride) {
    constexpr int WPB = 8;
    constexpr int LPR = D / 8;          // lanes per row (16 for D=128, 8 for D=64)
    constexpr int RPI = 32 / LPR;       // rows per warp-iteration (2 or 4)
    __shared__ __align__(16) float2 wns[WPB][MAXD + RPI];
    int warp = threadIdx.x >> 5, lane = threadIdx.x & 31;
    int i = blockIdx.x * WPB + warp;
    int h = blockIdx.y;
    const __nv_bfloat16* WhH = Whb + h * (NN * D);
    const float* f2H = f2 + h * NN;
    float f1i = f1[h * NN + i];
    int d = g_deg[i];
    float2* w = wns[warp];
    const unsigned FULL = 0xffffffffu;

    // pass A: e = leakyrelu(f1_i + f2_j), track max
    float m = -3.4e38f;
    for (int k = lane; k < d; k += 32) {
        int j = g_nbr[i * MAXD + k];
        float e = f1i + f2H[j];
        e = (e > 0.0f) ? e : 0.2f * e;
        m = fmaxf(m, e);
        w[k] = make_float2(e, __int_as_float(j * (D * 2)));
    }
#pragma unroll
    for (int o = 16; o; o >>= 1) m = fmaxf(m, __shfl_xor_sync(FULL, m, o));

    // pass B: exp + sum
    float s = 0.0f;
    for (int k = lane; k < d; k += 32) {
        float v = __expf(w[k].x - m);
        w[k].x = v;
        s += v;
    }
#pragma unroll
    for (int o = 16; o; o >>= 1) s += __shfl_xor_sync(FULL, s, o);
    // zero-pad so gather loop needs no tail (wk=0, off=0 -> harmless row-0 load)
    if (lane == 0) {
#pragma unroll
        for (int q = 0; q < RPI - 1; q++) w[d + q] = make_float2(0.0f, 0.0f);
    }
    __syncwarp();

    // pass C: gather. half = which of RPI rows this lane covers.
    int half = lane / LPR;
    int fl   = lane % LPR;
    const char* basep = (const char*)WhH + fl * 16;   // 8 bf16 = 16 B per lane
    unsigned long long acc2[4];
#pragma unroll
    for (int q = 0; q < 4; q++) acc2[q] = 0ull;

    if (d > 0) {
        int dR = (d + RPI - 1) / RPI * RPI;
#pragma unroll 4
        for (int k0 = 0; k0 < dR; k0 += RPI) {
            float2 p = w[k0 + half];
            unsigned long long wk2 = dup2(p.x);
            int off = __float_as_int(p.y);
            uint4 raw = *(const uint4*)(basep + off);
            acc2[0] = fma2(cvt2(raw.x), wk2, acc2[0]);
            acc2[1] = fma2(cvt2(raw.y), wk2, acc2[1]);
            acc2[2] = fma2(cvt2(raw.z), wk2, acc2[2]);
            acc2[3] = fma2(cvt2(raw.w), wk2, acc2[3]);
        }
    } else {
        // uniform attention over all nodes (softmax of constant row); never hot.
        if (half == 0) {
            for (int k = 0; k < NN; k++) {
                uint4 raw = *(const uint4*)(basep + k * (D * 2));
                unsigned long long one = dup2(1.0f);
                acc2[0] = fma2(cvt2(raw.x), one, acc2[0]);
                acc2[1] = fma2(cvt2(raw.y), one, acc2[1]);
                acc2[2] = fma2(cvt2(raw.z), one, acc2[2]);
                acc2[3] = fma2(cvt2(raw.w), one, acc2[3]);
            }
        }
    }

    // unpack + cross-half reduce
    float accf[8];
#pragma unroll
    for (int q = 0; q < 4; q++) {
        float2 t = unpk(acc2[q]);
        accf[2 * q] = t.x; accf[2 * q + 1] = t.y;
    }
#pragma unroll
    for (int o = LPR; o < 32; o <<= 1) {
#pragma unroll
        for (int q = 0; q < 8; q++)
            accf[q] += __shfl_down_sync(FULL, accf[q], o);
    }

    if (lane < LPR) {
        float inv = (d > 0) ? (1.0f / s) : (1.0f / NN);
#pragma unroll
        for (int q = 0; q < 8; q++) {
            float v = accf[q] * inv;
            accf[q] = (v > 0.0f) ? v : expm1f(v);
        }
        float* op = out + (long)i * iStride + h * hStride + lane * 8;
        *(float4*)op       = make_float4(accf[0], accf[1], accf[2], accf[3]);
        *(float4*)(op + 4) = make_float4(accf[4], accf[5], accf[6], accf[7]);
    }
}

// ---------------- launch ----------------
extern "C" void kernel_launch(void* const* d_in, const int* in_sizes, int n_in,
                              void* d_out, int out_size) {
    const float* x     = (const float*)d_in[0];
    const float* adj   = (const float*)d_in[1];
    const int*   obs   = (const int*)  d_in[2];
    // d_in[3] = s_mat (unused)
    const float* theta = (const float*)d_in[4];
    const float* W0    = (const float*)d_in[5];
    const float* a0    = (const float*)d_in[6];
    const float* W1    = (const float*)d_in[7];
    const float* a1    = (const float*)d_in[8];
    const float* Wo    = (const float*)d_in[9];
    const float* ao    = (const float*)d_in[10];
    float* out = (float*)d_out;

    void *pWhb, *pHa, *pHc, *pWhob, *pF1, *pF2, *pF1o, *pF2o;
    cudaGetSymbolAddress(&pWhb,  g_Whb);
    cudaGetSymbolAddress(&pHa,   g_ha);
    cudaGetSymbolAddress(&pHc,   g_hc);
    cudaGetSymbolAddress(&pWhob, g_Whob);
    cudaGetSymbolAddress(&pF1,   g_f1);
    cudaGetSymbolAddress(&pF2,   g_f2);
    cudaGetSymbolAddress(&pF1o,  g_f1o);
    cudaGetSymbolAddress(&pF2o,  g_f2o);

    thetaW_kernel<<<HH, DD>>>(theta, W0);
    build_csr_kernel<<<NN, 256>>>(adj);

    // ---- layer 0 (theta merged in epilogue) ----
    mma_gemm<64, 128, 16, 32, 64, true><<<dim3(1, NN / 64, HH), 128>>>(
        x, W0, (__nv_bfloat16*)pWhb, a0,
        (float*)pF1, (float*)pF2, NN, DD, FF,
        0L, (long)FF * DD, 2L * DD, obs);
    attn_warp<DD><<<dim3(NN / 8, HH), 256>>>((const __nv_bfloat16*)pWhb,
                                             (const float*)pF1, (const float*)pF2,
                                             (float*)pHa, DD, NN * DD);

    // ---- layer 1 (output written directly in concat layout) ----
    mma_gemm<64, 128, 16, 32, 64, false><<<dim3(1, NN / 64, HH), 128>>>(
        (const float*)pHa, W1, (__nv_bfloat16*)pWhb, a1,
        (float*)pF1, (float*)pF2, NN, DD, DD,
        (long)NN * DD, (long)DD * DD, 2L * DD, nullptr);
    attn_warp<DD><<<dim3(NN / 8, HH), 256>>>((const __nv_bfloat16*)pWhb,
                                             (const float*)pF1, (const float*)pF2,
                                             (float*)pHc, HH * DD, DD);

    // ---- output layer: split-K GEMM + combine ----
    mma_splitk<<<dim3(SPLITK, NN / 64), 128>>>(
        (const float*)pHc, Wo, NN, OUTD, HH * DD);
    out_epi<<<NN / 8, 256>>>(ao);
    attn_warp<OUTD><<<dim3(NN / 8, 1), 256>>>((const __nv_bfloat16*)pWhob,
                                              (const float*)pF1o, (const float*)pF2o,
                                              out, OUTD, 0);
    (void)in_sizes; (void)n_in; (void)out_size;
}

// round 9
// speedup vs baseline: 1.0275x; 1.0275x over previous
#include <cuda_runtime.h>
#include <cuda_bf16.h>

// Problem constants
#define NN   3072
#define FF   256
#define HH   8
#define DD   128
#define OUTD 64
#define MAXD 384
#define SPLITK 4

// ---------------- device scratch ----------------
__device__ __align__(16) __nv_bfloat16 g_Whb [HH * NN * DD];
__device__ __align__(16) float         g_ha  [HH * NN * DD];
__device__ __align__(16) float         g_hc  [NN * HH * DD];
__device__ __align__(16) float         g_who [SPLITK * NN * OUTD];
__device__ __align__(16) __nv_bfloat16 g_Whob[NN * OUTD];
__device__ __align__(16) float         g_tw  [HH * DD];       // theta @ W0 per head
__device__ float g_f1 [HH * NN];
__device__ float g_f2 [HH * NN];
__device__ float g_f1o[NN];
__device__ float g_f2o[NN];
__device__ int   g_nbr[NN * MAXD];
__device__ int   g_deg[NN];

// ---------------- theta @ W0 precompute (per head) ----------------
__global__ void thetaW_kernel(const float* __restrict__ theta,
                              const float* __restrict__ W0) {
    int h = blockIdx.x;
    int c = threadIdx.x;            // 0..DD-1
    float s = 0.0f;
    const float* Wh = W0 + (long)h * FF * DD + c;
#pragma unroll 4
    for (int k = 0; k < FF; k++) s += theta[k] * Wh[(long)k * DD];
    g_tw[h * DD + c] = s;
}

// ---------------- CSR build (float4) ----------------
__global__ void build_csr_kernel(const float* __restrict__ adj) {
    int i = blockIdx.x;
    __shared__ int cnt;
    if (threadIdx.x == 0) cnt = 0;
    __syncthreads();
    const float4* row = (const float4*)(adj + (long)i * NN);
    for (int q = threadIdx.x; q < NN / 4; q += blockDim.x) {
        float4 v = row[q];
        int j = 4 * q;
        if (v.x > 0.0f) { int p = atomicAdd(&cnt, 1); if (p < MAXD) g_nbr[i * MAXD + p] = j; }
        if (v.y > 0.0f) { int p = atomicAdd(&cnt, 1); if (p < MAXD) g_nbr[i * MAXD + p] = j + 1; }
        if (v.z > 0.0f) { int p = atomicAdd(&cnt, 1); if (p < MAXD) g_nbr[i * MAXD + p] = j + 2; }
        if (v.w > 0.0f) { int p = atomicAdd(&cnt, 1); if (p < MAXD) g_nbr[i * MAXD + p] = j + 3; }
    }
    __syncthreads();
    if (threadIdx.x == 0) g_deg[i] = cnt < MAXD ? cnt : MAXD;
}

// ---------------- mma / cp.async helpers ----------------
__device__ __forceinline__ unsigned f2tf(unsigned bits) {
    unsigned u;
    asm("cvt.rna.tf32.f32 %0, %1;" : "=r"(u) : "r"(bits));
    return u;
}
__device__ __forceinline__ void mma_tf32(float c[4], const unsigned a[4], const unsigned b[2]) {
    asm("mma.sync.aligned.m16n8k8.row.col.f32.tf32.tf32.f32 "
        "{%0,%1,%2,%3}, {%4,%5,%6,%7}, {%8,%9}, {%0,%1,%2,%3};"
        : "+f"(c[0]), "+f"(c[1]), "+f"(c[2]), "+f"(c[3])
        : "r"(a[0]), "r"(a[1]), "r"(a[2]), "r"(a[3]), "r"(b[0]), "r"(b[1]));
}
__device__ __forceinline__ void cpa16(void* smem_dst, const void* gsrc) {
    unsigned saddr = (unsigned)__cvta_generic_to_shared(smem_dst);
    asm volatile("cp.async.ca.shared.global [%0], [%1], 16;" :: "r"(saddr), "l"(gsrc));
}
__device__ __forceinline__ void cpa_commit() { asm volatile("cp.async.commit_group;"); }
template <int N>
__device__ __forceinline__ void cpa_wait() { asm volatile("cp.async.wait_group %0;" :: "n"(N)); }

// ---------------- f32x2 packed helpers (sm_103a FFMA2) ----------------
__device__ __forceinline__ unsigned long long fma2(unsigned long long a,
                                                   unsigned long long b,
                                                   unsigned long long c) {
    unsigned long long d;
    asm("fma.rn.f32x2 %0, %1, %2, %3;" : "=l"(d) : "l"(a), "l"(b), "l"(c));
    return d;
}
// bf16x2 word -> packed f32x2 {lo, hi} (exact)
__device__ __forceinline__ unsigned long long cvt2(unsigned u) {
    unsigned lo = u << 16;
    unsigned hi = u & 0xffff0000u;
    unsigned long long r;
    asm("mov.b64 %0, {%1, %2};" : "=l"(r) : "r"(lo), "r"(hi));
    return r;
}
__device__ __forceinline__ unsigned long long dup2(float f) {
    unsigned b = __float_as_uint(f);
    unsigned long long r;
    asm("mov.b64 %0, {%1, %2};" : "=l"(r) : "r"(b), "r"(b));
    return r;
}
__device__ __forceinline__ float2 unpk(unsigned long long p) {
    unsigned lo, hi;
    asm("mov.b64 {%0, %1}, %2;" : "=r"(lo), "=r"(hi) : "l"(p));
    return make_float2(__uint_as_float(lo), __uint_as_float(hi));
}

// ---------------- pipelined tf32 GEMM + fused epilogue ----------------
template <int BM, int BN, int BK, int WM, int WN, bool FUSE_THETA>
__global__ void mma_gemm(const float* __restrict__ A,
                         const float* __restrict__ B,
                         __nv_bfloat16* __restrict__ Cb,
                         const float* __restrict__ avec,
                         float* __restrict__ f1,
                         float* __restrict__ f2,
                         int M, int Nc, int K,
                         long strideA, long strideB, long strideAv,
                         const int* __restrict__ obs) {
    constexpr int WARPS_N = BN / WN;
    constexpr int WARPS_M = BM / WM;
    constexpr int THREADS = WARPS_M * WARPS_N * 32;
    constexpr int MT = WM / 16, NT = WN / 8;
    constexpr int AP = BK + 4;
    constexpr int BP = BN + 8;
    constexpr int A_OPS = BM * BK / (4 * THREADS);
    constexpr int B_OPS = BK * BN / (4 * THREADS);

    __shared__ unsigned As[2][BM][AP];
    __shared__ unsigned Bs[2][BK][BP];
    __shared__ float f1s[BM], f2s[BM];

    int z = blockIdx.z;
    A    += (long)z * strideA;
    B    += (long)z * strideB;
    avec += (long)z * strideAv;
    Cb   += (long)z * M * Nc;
    f1   += (long)z * M;
    f2   += (long)z * M;

    int tid  = threadIdx.x;
    int brow = blockIdx.y * BM;
    int warp = tid >> 5, lane = tid & 31;
    int gid  = lane >> 2, tig = lane & 3;
    int wm   = (warp / WARPS_N) * WM;
    int wn   = (warp % WARPS_N) * WN;

    if (tid < BM) { f1s[tid] = 0.0f; f2s[tid] = 0.0f; }

    float c[MT][NT][4];
#pragma unroll
    for (int i = 0; i < MT; i++)
#pragma unroll
        for (int j = 0; j < NT; j++)
#pragma unroll
            for (int q = 0; q < 4; q++) c[i][j][q] = 0.0f;

    const int KT = K / BK;
    auto issue = [&](int kt, int s) {
        int k0 = kt * BK;
#pragma unroll
        for (int l = 0; l < A_OPS; l++) {
            int idx = tid + l * THREADS;
            int r  = idx / (BK / 4);
            int c4 = idx % (BK / 4);
            cpa16(&As[s][r][c4 * 4], &A[(long)(brow + r) * K + k0 + c4 * 4]);
        }
#pragma unroll
        for (int l = 0; l < B_OPS; l++) {
            int idx = tid + l * THREADS;
            int r  = idx / (BN / 4);
            int c4 = idx % (BN / 4);
            cpa16(&Bs[s][r][c4 * 4], &B[(long)(k0 + r) * Nc + c4 * 4]);
        }
        cpa_commit();
    };
    auto compute = [&](int s) {
#pragma unroll
        for (int kk = 0; kk < BK; kk += 8) {
            unsigned a[MT][4], b[NT][2];
#pragma unroll
            for (int mt = 0; mt < MT; mt++) {
                int r0 = wm + mt * 16 + gid;
                a[mt][0] = f2tf(As[s][r0][kk + tig]);
                a[mt][1] = f2tf(As[s][r0 + 8][kk + tig]);
                a[mt][2] = f2tf(As[s][r0][kk + tig + 4]);
                a[mt][3] = f2tf(As[s][r0 + 8][kk + tig + 4]);
            }
#pragma unroll
            for (int nt = 0; nt < NT; nt++) {
                int cn = wn + nt * 8 + gid;
                b[nt][0] = f2tf(Bs[s][kk + tig][cn]);
                b[nt][1] = f2tf(Bs[s][kk + tig + 4][cn]);
            }
#pragma unroll
            for (int mt = 0; mt < MT; mt++)
#pragma unroll
                for (int nt = 0; nt < NT; nt++)
                    mma_tf32(c[mt][nt], a[mt], b[nt]);
        }
    };

    issue(0, 0);
    for (int kt = 0; kt < KT; kt++) {
        if (kt + 1 < KT) { issue(kt + 1, (kt + 1) & 1); cpa_wait<1>(); }
        else             { cpa_wait<0>(); }
        __syncthreads();
        compute(kt & 1);
        __syncthreads();
    }

    // ---- epilogue: (+theta) bf16 store + f1/f2 ----
#pragma unroll
    for (int mt = 0; mt < MT; mt++) {
        int rl0 = wm + mt * 16 + gid;
        int rl1 = rl0 + 8;
        bool s0 = false, s1 = false;
        if (FUSE_THETA) {
            s0 = (obs[brow + rl0] == 1);
            s1 = (obs[brow + rl1] == 1);
        }
        float p10 = 0.f, p20 = 0.f, p11 = 0.f, p21 = 0.f;
#pragma unroll
        for (int nt = 0; nt < NT; nt++) {
            int col = wn + nt * 8 + tig * 2;
            float c0 = c[mt][nt][0], c1 = c[mt][nt][1];
            float c2 = c[mt][nt][2], c3 = c[mt][nt][3];
            if (FUSE_THETA) {
                float tw0 = g_tw[z * DD + col], tw1 = g_tw[z * DD + col + 1];
                if (s0) { c0 += tw0; c1 += tw1; }
                if (s1) { c2 += tw0; c3 += tw1; }
            }
            float a0 = __ldg(&avec[col]),      a1 = __ldg(&avec[col + 1]);
            float b0 = __ldg(&avec[Nc + col]), b1 = __ldg(&avec[Nc + col + 1]);
            p10 += c0 * a0 + c1 * a1;
            p20 += c0 * b0 + c1 * b1;
            p11 += c2 * a0 + c3 * a1;
            p21 += c2 * b0 + c3 * b1;
            *(__nv_bfloat162*)&Cb[(long)(brow + rl0) * Nc + col] =
                __float22bfloat162_rn(make_float2(c0, c1));
            *(__nv_bfloat162*)&Cb[(long)(brow + rl1) * Nc + col] =
                __float22bfloat162_rn(make_float2(c2, c3));
        }
#pragma unroll
        for (int o = 2; o; o >>= 1) {
            p10 += __shfl_down_sync(0xffffffffu, p10, o, 4);
            p20 += __shfl_down_sync(0xffffffffu, p20, o, 4);
            p11 += __shfl_down_sync(0xffffffffu, p11, o, 4);
            p21 += __shfl_down_sync(0xffffffffu, p21, o, 4);
        }
        if (tig == 0) {
            atomicAdd(&f1s[rl0], p10);
            atomicAdd(&f2s[rl0], p20);
            atomicAdd(&f1s[rl1], p11);
            atomicAdd(&f2s[rl1], p21);
        }
    }
    __syncthreads();
    if (tid < BM) {
        f1[brow + tid] = f1s[tid];
        f2[brow + tid] = f2s[tid];
    }
}

// ---------------- split-K output GEMM (fp32 partials, no atomics) ----------------
__global__ void mma_splitk(const float* __restrict__ A,
                           const float* __restrict__ B,
                           int M, int Nc, int K) {
    constexpr int BM = 64, BN = 64, BK = 16;
    constexpr int THREADS = 128;
    constexpr int MT = 2, NT = 4;
    constexpr int AP = BK + 4;
    constexpr int BP = BN + 8;
    constexpr int A_OPS = BM * BK / (4 * THREADS);
    constexpr int B_OPS = BK * BN / (4 * THREADS);

    __shared__ unsigned As[2][BM][AP];
    __shared__ unsigned Bs[2][BK][BP];

    int tid  = threadIdx.x;
    int ksp  = blockIdx.x;
    int brow = blockIdx.y * BM;
    int kBeg = ksp * (K / SPLITK);
    int warp = tid >> 5, lane = tid & 31;
    int gid  = lane >> 2, tig = lane & 3;
    int wm   = (warp / 2) * 32;
    int wn   = (warp % 2) * 32;
    float* Cf = g_who + (long)ksp * M * Nc;

    float c[MT][NT][4];
#pragma unroll
    for (int i = 0; i < MT; i++)
#pragma unroll
        for (int j = 0; j < NT; j++)
#pragma unroll
            for (int q = 0; q < 4; q++) c[i][j][q] = 0.0f;

    const int KT = (K / SPLITK) / BK;
    auto issue = [&](int kt, int s) {
        int k0 = kBeg + kt * BK;
#pragma unroll
        for (int l = 0; l < A_OPS; l++) {
            int idx = tid + l * THREADS;
            int r  = idx / (BK / 4);
            int c4 = idx % (BK / 4);
            cpa16(&As[s][r][c4 * 4], &A[(long)(brow + r) * K + k0 + c4 * 4]);
        }
#pragma unroll
        for (int l = 0; l < B_OPS; l++) {
            int idx = tid + l * THREADS;
            int r  = idx / (BN / 4);
            int c4 = idx % (BN / 4);
            cpa16(&Bs[s][r][c4 * 4], &B[(long)(k0 + r) * Nc + c4 * 4]);
        }
        cpa_commit();
    };
    auto compute = [&](int s) {
#pragma unroll
        for (int kk = 0; kk < BK; kk += 8) {
            unsigned a[MT][4], b[NT][2];
#pragma unroll
            for (int mt = 0; mt < MT; mt++) {
                int r0 = wm + mt * 16 + gid;
                a[mt][0] = f2tf(As[s][r0][kk + tig]);
                a[mt][1] = f2tf(As[s][r0 + 8][kk + tig]);
                a[mt][2] = f2tf(As[s][r0][kk + tig + 4]);
                a[mt][3] = f2tf(As[s][r0 + 8][kk + tig + 4]);
            }
#pragma unroll
            for (int nt = 0; nt < NT; nt++) {
                int cn = wn + nt * 8 + gid;
                b[nt][0] = f2tf(Bs[s][kk + tig][cn]);
                b[nt][1] = f2tf(Bs[s][kk + tig + 4][cn]);
            }
#pragma unroll
            for (int mt = 0; mt < MT; mt++)
#pragma unroll
                for (int nt = 0; nt < NT; nt++)
                    mma_tf32(c[mt][nt], a[mt], b[nt]);
        }
    };

    issue(0, 0);
    for (int kt = 0; kt < KT; kt++) {
        if (kt + 1 < KT) { issue(kt + 1, (kt + 1) & 1); cpa_wait<1>(); }
        else             { cpa_wait<0>(); }
        __syncthreads();
        compute(kt & 1);
        __syncthreads();
    }

#pragma unroll
    for (int mt = 0; mt < MT; mt++) {
        int rl0 = brow + wm + mt * 16 + gid;
        int rl1 = rl0 + 8;
#pragma unroll
        for (int nt = 0; nt < NT; nt++) {
            int col = wn + nt * 8 + tig * 2;
            *(float2*)&Cf[(long)rl0 * Nc + col] = make_float2(c[mt][nt][0], c[mt][nt][1]);
            *(float2*)&Cf[(long)rl1 * Nc + col] = make_float2(c[mt][nt][2], c[mt][nt][3]);
        }
    }
}

// ---------------- combine split-K partials + f1o/f2o + bf16 ----------------
__global__ void out_epi(const float* __restrict__ ao) {
    int warp = threadIdx.x >> 5, lane = threadIdx.x & 31;
    int r = blockIdx.x * 8 + warp;
    float v0 = 0.f, v1 = 0.f;
#pragma unroll
    for (int s = 0; s < SPLITK; s++) {
        const float* row = g_who + (long)s * NN * OUTD + (long)r * OUTD;
        v0 += row[lane];
        v1 += row[lane + 32];
    }
    float p1 = v0 * __ldg(&ao[lane]) + v1 * __ldg(&ao[lane + 32]);
    float p2 = v0 * __ldg(&ao[OUTD + lane]) + v1 * __ldg(&ao[OUTD + lane + 32]);
#pragma unroll
    for (int o = 16; o; o >>= 1) {
        p1 += __shfl_xor_sync(0xffffffffu, p1, o);
        p2 += __shfl_xor_sync(0xffffffffu, p2, o);
    }
    if (lane == 0) { g_f1o[r] = p1; g_f2o[r] = p2; }
    g_Whob[r * OUTD + lane]      = __float2bfloat16(v0);
    g_Whob[r * OUTD + lane + 32] = __float2bfloat16(v1);
}

// ---------------- warp-per-(i,h) sparse attention + ELU ----------------
// block = 256 (8 warps). Gather: RPI rows per warp-iteration, LPR lanes per row,
// 8 bf16 feats per lane (LDG.128 covers the whole row). FFMA2 accumulate.
template <int D>
__global__ void attn_warp(const __nv_bfloat16* __restrict__ Whb,
                          const float* __restrict__ f1,
                          const float* __restrict__ f2,
                          float* __restrict__ out,
                          int iStride, int hStride) {
    constexpr int WPB = 8;
    constexpr int LPR = D / 8;          // lanes per row (16 for D=128, 8 for D=64)
    constexpr int RPI = 32 / LPR;       // rows per warp-iteration (2 or 4)
    __shared__ __align__(16) float2 wns[WPB][MAXD + RPI];
    int warp = threadIdx.x >> 5, lane = threadIdx.x & 31;
    int i = blockIdx.x * WPB + warp;
    int h = blockIdx.y;
    const __nv_bfloat16* WhH = Whb + h * (NN * D);
    const float* f2H = f2 + h * NN;
    float f1i = f1[h * NN + i];
    int d = g_deg[i];
    float2* w = wns[warp];
    const unsigned FULL = 0xffffffffu;

    // pass A: e = leakyrelu(f1_i + f2_j), track max
    float m = -3.4e38f;
    for (int k = lane; k < d; k += 32) {
        int j = g_nbr[i * MAXD + k];
        float e = f1i + f2H[j];
        e = (e > 0.0f) ? e : 0.2f * e;
        m = fmaxf(m, e);
        w[k] = make_float2(e, __int_as_float(j * (D * 2)));
    }
#pragma unroll
    for (int o = 16; o; o >>= 1) m = fmaxf(m, __shfl_xor_sync(FULL, m, o));

    // pass B: exp + sum
    float s = 0.0f;
    for (int k = lane; k < d; k += 32) {
        float v = __expf(w[k].x - m);
        w[k].x = v;
        s += v;
    }
#pragma unroll
    for (int o = 16; o; o >>= 1) s += __shfl_xor_sync(FULL, s, o);
    // zero-pad so gather loop needs no tail (wk=0, off=0 -> harmless row-0 load)
    if (lane == 0) {
#pragma unroll
        for (int q = 0; q < RPI - 1; q++) w[d + q] = make_float2(0.0f, 0.0f);
    }
    __syncwarp();

    // pass C: gather. half = which of RPI rows this lane covers.
    int half = lane / LPR;
    int fl   = lane % LPR;
    const char* basep = (const char*)WhH + fl * 16;   // 8 bf16 = 16 B per lane
    unsigned long long acc2[4];
#pragma unroll
    for (int q = 0; q < 4; q++) acc2[q] = 0ull;

    if (d > 0) {
        int dR = (d + RPI - 1) / RPI * RPI;
#pragma unroll 4
        for (int k0 = 0; k0 < dR; k0 += RPI) {
            float2 p = w[k0 + half];
            unsigned long long wk2 = dup2(p.x);
            int off = __float_as_int(p.y);
            uint4 raw = *(const uint4*)(basep + off);
            acc2[0] = fma2(cvt2(raw.x), wk2, acc2[0]);
            acc2[1] = fma2(cvt2(raw.y), wk2, acc2[1]);
            acc2[2] = fma2(cvt2(raw.z), wk2, acc2[2]);
            acc2[3] = fma2(cvt2(raw.w), wk2, acc2[3]);
        }
    } else {
        // uniform attention over all nodes (softmax of constant row); never hot.
        if (half == 0) {
            for (int k = 0; k < NN; k++) {
                uint4 raw = *(const uint4*)(basep + k * (D * 2));
                unsigned long long one = dup2(1.0f);
                acc2[0] = fma2(cvt2(raw.x), one, acc2[0]);
                acc2[1] = fma2(cvt2(raw.y), one, acc2[1]);
                acc2[2] = fma2(cvt2(raw.z), one, acc2[2]);
                acc2[3] = fma2(cvt2(raw.w), one, acc2[3]);
            }
        }
    }

    // unpack + cross-half reduce
    float accf[8];
#pragma unroll
    for (int q = 0; q < 4; q++) {
        float2 t = unpk(acc2[q]);
        accf[2 * q] = t.x; accf[2 * q + 1] = t.y;
    }
#pragma unroll
    for (int o = LPR; o < 32; o <<= 1) {
#pragma unroll
        for (int q = 0; q < 8; q++)
            accf[q] += __shfl_down_sync(FULL, accf[q], o);
    }

    if (lane < LPR) {
        float inv = (d > 0) ? (1.0f / s) : (1.0f / NN);
#pragma unroll
        for (int q = 0; q < 8; q++) {
            float v = accf[q] * inv;
            accf[q] = (v > 0.0f) ? v : expm1f(v);
        }
        float* op = out + (long)i * iStride + h * hStride + lane * 8;
        *(float4*)op       = make_float4(accf[0], accf[1], accf[2], accf[3]);
        *(float4*)(op + 4) = make_float4(accf[4], accf[5], accf[6], accf[7]);
    }
}

// ---------------- launch ----------------
extern "C" void kernel_launch(void* const* d_in, const int* in_sizes, int n_in,
                              void* d_out, int out_size) {
    const float* x     = (const float*)d_in[0];
    const float* adj   = (const float*)d_in[1];
    const int*   obs   = (const int*)  d_in[2];
    // d_in[3] = s_mat (unused)
    const float* theta = (const float*)d_in[4];
    const float* W0    = (const float*)d_in[5];
    const float* a0    = (const float*)d_in[6];
    const float* W1    = (const float*)d_in[7];
    const float* a1    = (const float*)d_in[8];
    const float* Wo    = (const float*)d_in[9];
    const float* ao    = (const float*)d_in[10];
    float* out = (float*)d_out;

    void *pWhb, *pHa, *pHc, *pWhob, *pF1, *pF2, *pF1o, *pF2o;
    cudaGetSymbolAddress(&pWhb,  g_Whb);
    cudaGetSymbolAddress(&pHa,   g_ha);
    cudaGetSymbolAddress(&pHc,   g_hc);
    cudaGetSymbolAddress(&pWhob, g_Whob);
    cudaGetSymbolAddress(&pF1,   g_f1);
    cudaGetSymbolAddress(&pF2,   g_f2);
    cudaGetSymbolAddress(&pF1o,  g_f1o);
    cudaGetSymbolAddress(&pF2o,  g_f2o);

    thetaW_kernel<<<HH, DD>>>(theta, W0);
    build_csr_kernel<<<NN, 256>>>(adj);

    // ---- layer 0 (theta merged in epilogue) ----
    mma_gemm<64, 128, 16, 32, 64, true><<<dim3(1, NN / 64, HH), 128>>>(
        x, W0, (__nv_bfloat16*)pWhb, a0,
        (float*)pF1, (float*)pF2, NN, DD, FF,
        0L, (long)FF * DD, 2L * DD, obs);
    attn_warp<DD><<<dim3(NN / 8, HH), 256>>>((const __nv_bfloat16*)pWhb,
                                             (const float*)pF1, (const float*)pF2,
                                             (float*)pHa, DD, NN * DD);

    // ---- layer 1 (output written directly in concat layout) ----
    mma_gemm<64, 128, 16, 32, 64, false><<<dim3(1, NN / 64, HH), 128>>>(
        (const float*)pHa, W1, (__nv_bfloat16*)pWhb, a1,
        (float*)pF1, (float*)pF2, NN, DD, DD,
        (long)NN * DD, (long)DD * DD, 2L * DD, nullptr);
    attn_warp<DD><<<dim3(NN / 8, HH), 256>>>((const __nv_bfloat16*)pWhb,
                                             (const float*)pF1, (const float*)pF2,
                                             (float*)pHc, HH * DD, DD);

    // ---- output layer: split-K GEMM + combine ----
    mma_splitk<<<dim3(SPLITK, NN / 64), 128>>>(
        (const float*)pHc, Wo, NN, OUTD, HH * DD);
    out_epi<<<NN / 8, 256>>>(ao);
    attn_warp<OUTD><<<dim3(NN / 8, 1), 256>>>((const __nv_bfloat16*)pWhob,
                                              (const float*)pF1o, (const float*)pF2o,
                                              out, OUTD, 0);
    (void)in_sizes; (void)n_in; (void)out_size;
}

// round 10
// speedup vs baseline: 1.0605x; 1.0321x over previous
#include <cuda_runtime.h>
#include <cuda_bf16.h>

// Problem constants
#define NN   3072
#define FF   256
#define HH   8
#define DD   128
#define OUTD 64
#define MAXD 384
#define SPLITK 4

// ---------------- device scratch ----------------
__device__ __align__(16) __nv_bfloat16 g_Whb [HH * NN * DD];
__device__ __align__(16) float         g_ha  [HH * NN * DD];
__device__ __align__(16) float         g_hc  [NN * HH * DD];
__device__ __align__(16) float         g_who [SPLITK * NN * OUTD];
__device__ __align__(16) __nv_bfloat16 g_Whob[NN * OUTD];
__device__ __align__(16) float         g_tw  [HH * DD];       // theta @ W0 per head
__device__ float g_f1 [HH * NN];
__device__ float g_f2 [HH * NN];
__device__ float g_f1o[NN];
__device__ float g_f2o[NN];
__device__ int   g_nbr[NN * MAXD];
__device__ int   g_deg[NN];

// ---------------- theta @ W0 precompute (per head) ----------------
__global__ void thetaW_kernel(const float* __restrict__ theta,
                              const float* __restrict__ W0) {
    int h = blockIdx.x;
    int c = threadIdx.x;            // 0..DD-1
    float s = 0.0f;
    const float* Wh = W0 + (long)h * FF * DD + c;
#pragma unroll 4
    for (int k = 0; k < FF; k++) s += theta[k] * Wh[(long)k * DD];
    g_tw[h * DD + c] = s;
}

// ---------------- CSR build (float4) ----------------
__global__ void build_csr_kernel(const float* __restrict__ adj) {
    int i = blockIdx.x;
    __shared__ int cnt;
    if (threadIdx.x == 0) cnt = 0;
    __syncthreads();
    const float4* row = (const float4*)(adj + (long)i * NN);
    for (int q = threadIdx.x; q < NN / 4; q += blockDim.x) {
        float4 v = row[q];
        int j = 4 * q;
        if (v.x > 0.0f) { int p = atomicAdd(&cnt, 1); if (p < MAXD) g_nbr[i * MAXD + p] = j; }
        if (v.y > 0.0f) { int p = atomicAdd(&cnt, 1); if (p < MAXD) g_nbr[i * MAXD + p] = j + 1; }
        if (v.z > 0.0f) { int p = atomicAdd(&cnt, 1); if (p < MAXD) g_nbr[i * MAXD + p] = j + 2; }
        if (v.w > 0.0f) { int p = atomicAdd(&cnt, 1); if (p < MAXD) g_nbr[i * MAXD + p] = j + 3; }
    }
    __syncthreads();
    if (threadIdx.x == 0) g_deg[i] = cnt < MAXD ? cnt : MAXD;
}

// ---------------- mma / cp.async helpers ----------------
__device__ __forceinline__ unsigned f2tf(unsigned bits) {
    unsigned u;
    asm("cvt.rna.tf32.f32 %0, %1;" : "=r"(u) : "r"(bits));
    return u;
}
__device__ __forceinline__ void mma_tf32(float c[4], const unsigned a[4], const unsigned b[2]) {
    asm("mma.sync.aligned.m16n8k8.row.col.f32.tf32.tf32.f32 "
        "{%0,%1,%2,%3}, {%4,%5,%6,%7}, {%8,%9}, {%0,%1,%2,%3};"
        : "+f"(c[0]), "+f"(c[1]), "+f"(c[2]), "+f"(c[3])
        : "r"(a[0]), "r"(a[1]), "r"(a[2]), "r"(a[3]), "r"(b[0]), "r"(b[1]));
}
__device__ __forceinline__ void cpa16(void* smem_dst, const void* gsrc) {
    unsigned saddr = (unsigned)__cvta_generic_to_shared(smem_dst);
    asm volatile("cp.async.ca.shared.global [%0], [%1], 16;" :: "r"(saddr), "l"(gsrc));
}
__device__ __forceinline__ void cpa_commit() { asm volatile("cp.async.commit_group;"); }
template <int N>
__device__ __forceinline__ void cpa_wait() { asm volatile("cp.async.wait_group %0;" :: "n"(N)); }

// ---------------- f32x2 packed helpers (sm_103a FFMA2) ----------------
__device__ __forceinline__ unsigned long long fma2(unsigned long long a,
                                                   unsigned long long b,
                                                   unsigned long long c) {
    unsigned long long d;
    asm("fma.rn.f32x2 %0, %1, %2, %3;" : "=l"(d) : "l"(a), "l"(b), "l"(c));
    return d;
}
// bf16x2 word -> packed f32x2 {lo, hi} (exact)
__device__ __forceinline__ unsigned long long cvt2(unsigned u) {
    unsigned lo = u << 16;
    unsigned hi = u & 0xffff0000u;
    unsigned long long r;
    asm("mov.b64 %0, {%1, %2};" : "=l"(r) : "r"(lo), "r"(hi));
    return r;
}
__device__ __forceinline__ unsigned long long dup2(float f) {
    unsigned b = __float_as_uint(f);
    unsigned long long r;
    asm("mov.b64 %0, {%1, %2};" : "=l"(r) : "r"(b), "r"(b));
    return r;
}
__device__ __forceinline__ float2 unpk(unsigned long long p) {
    unsigned lo, hi;
    asm("mov.b64 {%0, %1}, %2;" : "=r"(lo), "=r"(hi) : "l"(p));
    return make_float2(__uint_as_float(lo), __uint_as_float(hi));
}

// ---------------- 3-stage pipelined tf32 GEMM + fused epilogue ----------------
template <int BM, int BN, int BK, int WM, int WN, bool FUSE_THETA>
__global__ void mma_gemm(const float* __restrict__ A,
                         const float* __restrict__ B,
                         __nv_bfloat16* __restrict__ Cb,
                         const float* __restrict__ avec,
                         float* __restrict__ f1,
                         float* __restrict__ f2,
                         int M, int Nc, int K,
                         long strideA, long strideB, long strideAv,
                         const int* __restrict__ obs) {
    constexpr int WARPS_N = BN / WN;
    constexpr int WARPS_M = BM / WM;
    constexpr int THREADS = WARPS_M * WARPS_N * 32;
    constexpr int MT = WM / 16, NT = WN / 8;
    constexpr int AP = BK + 4;
    constexpr int BP = BN + 8;
    constexpr int A_OPS = BM * BK / (4 * THREADS);
    constexpr int B_OPS = BK * BN / (4 * THREADS);
    constexpr int ST = 3;

    __shared__ unsigned As[ST][BM][AP];
    __shared__ unsigned Bs[ST][BK][BP];
    __shared__ float f1s[BM], f2s[BM];

    int z = blockIdx.z;
    A    += (long)z * strideA;
    B    += (long)z * strideB;
    avec += (long)z * strideAv;
    Cb   += (long)z * M * Nc;
    f1   += (long)z * M;
    f2   += (long)z * M;

    int tid  = threadIdx.x;
    int brow = blockIdx.y * BM;
    int warp = tid >> 5, lane = tid & 31;
    int gid  = lane >> 2, tig = lane & 3;
    int wm   = (warp / WARPS_N) * WM;
    int wn   = (warp % WARPS_N) * WN;

    if (tid < BM) { f1s[tid] = 0.0f; f2s[tid] = 0.0f; }

    float c[MT][NT][4];
#pragma unroll
    for (int i = 0; i < MT; i++)
#pragma unroll
        for (int j = 0; j < NT; j++)
#pragma unroll
            for (int q = 0; q < 4; q++) c[i][j][q] = 0.0f;

    const int KT = K / BK;
    auto issue = [&](int kt, int s) {
        int k0 = kt * BK;
#pragma unroll
        for (int l = 0; l < A_OPS; l++) {
            int idx = tid + l * THREADS;
            int r  = idx / (BK / 4);
            int c4 = idx % (BK / 4);
            cpa16(&As[s][r][c4 * 4], &A[(long)(brow + r) * K + k0 + c4 * 4]);
        }
#pragma unroll
        for (int l = 0; l < B_OPS; l++) {
            int idx = tid + l * THREADS;
            int r  = idx / (BN / 4);
            int c4 = idx % (BN / 4);
            cpa16(&Bs[s][r][c4 * 4], &B[(long)(k0 + r) * Nc + c4 * 4]);
        }
        cpa_commit();
    };
    auto compute = [&](int s) {
#pragma unroll
        for (int kk = 0; kk < BK; kk += 8) {
            unsigned a[MT][4], b[NT][2];
#pragma unroll
            for (int mt = 0; mt < MT; mt++) {
                int r0 = wm + mt * 16 + gid;
                a[mt][0] = f2tf(As[s][r0][kk + tig]);
                a[mt][1] = f2tf(As[s][r0 + 8][kk + tig]);
                a[mt][2] = f2tf(As[s][r0][kk + tig + 4]);
                a[mt][3] = f2tf(As[s][r0 + 8][kk + tig + 4]);
            }
#pragma unroll
            for (int nt = 0; nt < NT; nt++) {
                int cn = wn + nt * 8 + gid;
                b[nt][0] = f2tf(Bs[s][kk + tig][cn]);
                b[nt][1] = f2tf(Bs[s][kk + tig + 4][cn]);
            }
#pragma unroll
            for (int mt = 0; mt < MT; mt++)
#pragma unroll
                for (int nt = 0; nt < NT; nt++)
                    mma_tf32(c[mt][nt], a[mt], b[nt]);
        }
    };

    issue(0, 0);
    if (KT > 1) issue(1, 1);
    for (int kt = 0; kt < KT; kt++) {
        if (kt == KT - 1) cpa_wait<0>(); else cpa_wait<1>();
        __syncthreads();
        if (kt + 2 < KT) issue(kt + 2, (kt + 2) % ST);
        compute(kt % ST);
        __syncthreads();
    }

    // ---- epilogue: (+theta) bf16 store + f1/f2 ----
#pragma unroll
    for (int mt = 0; mt < MT; mt++) {
        int rl0 = wm + mt * 16 + gid;
        int rl1 = rl0 + 8;
        bool s0 = false, s1 = false;
        if (FUSE_THETA) {
            s0 = (obs[brow + rl0] == 1);
            s1 = (obs[brow + rl1] == 1);
        }
        float p10 = 0.f, p20 = 0.f, p11 = 0.f, p21 = 0.f;
#pragma unroll
        for (int nt = 0; nt < NT; nt++) {
            int col = wn + nt * 8 + tig * 2;
            float c0 = c[mt][nt][0], c1 = c[mt][nt][1];
            float c2 = c[mt][nt][2], c3 = c[mt][nt][3];
            if (FUSE_THETA) {
                float tw0 = g_tw[z * DD + col], tw1 = g_tw[z * DD + col + 1];
                if (s0) { c0 += tw0; c1 += tw1; }
                if (s1) { c2 += tw0; c3 += tw1; }
            }
            float a0 = __ldg(&avec[col]),      a1 = __ldg(&avec[col + 1]);
            float b0 = __ldg(&avec[Nc + col]), b1 = __ldg(&avec[Nc + col + 1]);
            p10 += c0 * a0 + c1 * a1;
            p20 += c0 * b0 + c1 * b1;
            p11 += c2 * a0 + c3 * a1;
            p21 += c2 * b0 + c3 * b1;
            *(__nv_bfloat162*)&Cb[(long)(brow + rl0) * Nc + col] =
                __float22bfloat162_rn(make_float2(c0, c1));
            *(__nv_bfloat162*)&Cb[(long)(brow + rl1) * Nc + col] =
                __float22bfloat162_rn(make_float2(c2, c3));
        }
#pragma unroll
        for (int o = 2; o; o >>= 1) {
            p10 += __shfl_down_sync(0xffffffffu, p10, o, 4);
            p20 += __shfl_down_sync(0xffffffffu, p20, o, 4);
            p11 += __shfl_down_sync(0xffffffffu, p11, o, 4);
            p21 += __shfl_down_sync(0xffffffffu, p21, o, 4);
        }
        if (tig == 0) {
            atomicAdd(&f1s[rl0], p10);
            atomicAdd(&f2s[rl0], p20);
            atomicAdd(&f1s[rl1], p11);
            atomicAdd(&f2s[rl1], p21);
        }
    }
    __syncthreads();
    if (tid < BM) {
        f1[brow + tid] = f1s[tid];
        f2[brow + tid] = f2s[tid];
    }
}

// ---------------- split-K output GEMM (fp32 partials, no atomics) ----------------
__global__ void mma_splitk(const float* __restrict__ A,
                           const float* __restrict__ B,
                           int M, int Nc, int K) {
    constexpr int BM = 64, BN = 64, BK = 16;
    constexpr int THREADS = 128;
    constexpr int MT = 2, NT = 4;
    constexpr int AP = BK + 4;
    constexpr int BP = BN + 8;
    constexpr int A_OPS = BM * BK / (4 * THREADS);
    constexpr int B_OPS = BK * BN / (4 * THREADS);
    constexpr int ST = 3;

    __shared__ unsigned As[ST][BM][AP];
    __shared__ unsigned Bs[ST][BK][BP];

    int tid  = threadIdx.x;
    int ksp  = blockIdx.x;
    int brow = blockIdx.y * BM;
    int kBeg = ksp * (K / SPLITK);
    int warp = tid >> 5, lane = tid & 31;
    int gid  = lane >> 2, tig = lane & 3;
    int wm   = (warp / 2) * 32;
    int wn   = (warp % 2) * 32;
    float* Cf = g_who + (long)ksp * M * Nc;

    float c[MT][NT][4];
#pragma unroll
    for (int i = 0; i < MT; i++)
#pragma unroll
        for (int j = 0; j < NT; j++)
#pragma unroll
            for (int q = 0; q < 4; q++) c[i][j][q] = 0.0f;

    const int KT = (K / SPLITK) / BK;
    auto issue = [&](int kt, int s) {
        int k0 = kBeg + kt * BK;
#pragma unroll
        for (int l = 0; l < A_OPS; l++) {
            int idx = tid + l * THREADS;
            int r  = idx / (BK / 4);
            int c4 = idx % (BK / 4);
            cpa16(&As[s][r][c4 * 4], &A[(long)(brow + r) * K + k0 + c4 * 4]);
        }
#pragma unroll
        for (int l = 0; l < B_OPS; l++) {
            int idx = tid + l * THREADS;
            int r  = idx / (BN / 4);
            int c4 = idx % (BN / 4);
            cpa16(&Bs[s][r][c4 * 4], &B[(long)(k0 + r) * Nc + c4 * 4]);
        }
        cpa_commit();
    };
    auto compute = [&](int s) {
#pragma unroll
        for (int kk = 0; kk < BK; kk += 8) {
            unsigned a[MT][4], b[NT][2];
#pragma unroll
            for (int mt = 0; mt < MT; mt++) {
                int r0 = wm + mt * 16 + gid;
                a[mt][0] = f2tf(As[s][r0][kk + tig]);
                a[mt][1] = f2tf(As[s][r0 + 8][kk + tig]);
                a[mt][2] = f2tf(As[s][r0][kk + tig + 4]);
                a[mt][3] = f2tf(As[s][r0 + 8][kk + tig + 4]);
            }
#pragma unroll
            for (int nt = 0; nt < NT; nt++) {
                int cn = wn + nt * 8 + gid;
                b[nt][0] = f2tf(Bs[s][kk + tig][cn]);
                b[nt][1] = f2tf(Bs[s][kk + tig + 4][cn]);
            }
#pragma unroll
            for (int mt = 0; mt < MT; mt++)
#pragma unroll
                for (int nt = 0; nt < NT; nt++)
                    mma_tf32(c[mt][nt], a[mt], b[nt]);
        }
    };

    issue(0, 0);
    if (KT > 1) issue(1, 1);
    for (int kt = 0; kt < KT; kt++) {
        if (kt == KT - 1) cpa_wait<0>(); else cpa_wait<1>();
        __syncthreads();
        if (kt + 2 < KT) issue(kt + 2, (kt + 2) % ST);
        compute(kt % ST);
        __syncthreads();
    }

#pragma unroll
    for (int mt = 0; mt < MT; mt++) {
        int rl0 = brow + wm + mt * 16 + gid;
        int rl1 = rl0 + 8;
#pragma unroll
        for (int nt = 0; nt < NT; nt++) {
            int col = wn + nt * 8 + tig * 2;
            *(float2*)&Cf[(long)rl0 * Nc + col] = make_float2(c[mt][nt][0], c[mt][nt][1]);
            *(float2*)&Cf[(long)rl1 * Nc + col] = make_float2(c[mt][nt][2], c[mt][nt][3]);
        }
    }
}

// ---------------- combine split-K partials + f1o/f2o + bf16 ----------------
__global__ void out_epi(const float* __restrict__ ao) {
    int warp = threadIdx.x >> 5, lane = threadIdx.x & 31;
    int r = blockIdx.x * 8 + warp;
    float v0 = 0.f, v1 = 0.f;
#pragma unroll
    for (int s = 0; s < SPLITK; s++) {
        const float* row = g_who + (long)s * NN * OUTD + (long)r * OUTD;
        v0 += row[lane];
        v1 += row[lane + 32];
    }
    float p1 = v0 * __ldg(&ao[lane]) + v1 * __ldg(&ao[lane + 32]);
    float p2 = v0 * __ldg(&ao[OUTD + lane]) + v1 * __ldg(&ao[OUTD + lane + 32]);
#pragma unroll
    for (int o = 16; o; o >>= 1) {
        p1 += __shfl_xor_sync(0xffffffffu, p1, o);
        p2 += __shfl_xor_sync(0xffffffffu, p2, o);
    }
    if (lane == 0) { g_f1o[r] = p1; g_f2o[r] = p2; }
    g_Whob[r * OUTD + lane]      = __float2bfloat16(v0);
    g_Whob[r * OUTD + lane + 32] = __float2bfloat16(v1);
}

// ---------------- warp-per-(i,h) sparse attention + ELU (R7 shape + FFMA2) ----------------
// block = 256 (8 warps), grid = (NN/8, nHeads). 1 row per warp; 32 lanes span the row.
template <int D>
__global__ void attn_warp(const __nv_bfloat16* __restrict__ Whb,
                          const float* __restrict__ f1,
                          const float* __restrict__ f2,
                          float* __restrict__ out,
                          int iStride, int hStride) {
    constexpr int WPB = 8;
    constexpr int FPL = D / 32;          // floats per lane: 4 (D=128) or 2 (D=64)
    __shared__ __align__(16) float2 wns[WPB][MAXD];
    int warp = threadIdx.x >> 5, lane = threadIdx.x & 31;
    int i = blockIdx.x * WPB + warp;
    int h = blockIdx.y;
    const __nv_bfloat16* WhH = Whb + h * (NN * D);
    const float* f2H = f2 + h * NN;
    float f1i = f1[h * NN + i];
    int d = g_deg[i];
    float2* w = wns[warp];
    const unsigned FULL = 0xffffffffu;

    // pass A: e = leakyrelu(f1_i + f2_j), track max
    float m = -3.4e38f;
    for (int k = lane; k < d; k += 32) {
        int j = g_nbr[i * MAXD + k];
        float e = f1i + f2H[j];
        e = (e > 0.0f) ? e : 0.2f * e;
        m = fmaxf(m, e);
        w[k] = make_float2(e, __int_as_float(j * (D * 2)));
    }
#pragma unroll
    for (int o = 16; o; o >>= 1) m = fmaxf(m, __shfl_xor_sync(FULL, m, o));

    // pass B: exp + sum
    float s = 0.0f;
    for (int k = lane; k < d; k += 32) {
        float v = __expf(w[k].x - m);
        w[k].x = v;
        s += v;
    }
#pragma unroll
    for (int o = 16; o; o >>= 1) s += __shfl_xor_sync(FULL, s, o);
    __syncwarp();

    // pass C: gather — all 32 lanes per neighbor, FPL feats/lane, packed FFMA2
    const char* basep = (const char*)WhH + lane * (FPL * 2);
    unsigned long long acc2[FPL / 2];
#pragma unroll
    for (int q = 0; q < FPL / 2; q++) acc2[q] = 0ull;

    if (d > 0) {
#pragma unroll 8
        for (int k = 0; k < d; k++) {
            float2 p = w[k];
            unsigned long long wk2 = dup2(p.x);
            int off = __float_as_int(p.y);
            if (FPL == 4) {
                uint2 raw = *(const uint2*)(basep + off);
                acc2[0] = fma2(cvt2(raw.x), wk2, acc2[0]);
                acc2[1] = fma2(cvt2(raw.y), wk2, acc2[1]);
            } else {
                unsigned raw = *(const unsigned*)(basep + off);
                acc2[0] = fma2(cvt2(raw), wk2, acc2[0]);
            }
        }
    } else {
        // uniform attention over all nodes (softmax of constant row)
        unsigned long long one = dup2(1.0f);
        for (int k = 0; k < NN; k++) {
            if (FPL == 4) {
                uint2 raw = *(const uint2*)(basep + k * (D * 2));
                acc2[0] = fma2(cvt2(raw.x), one, acc2[0]);
                acc2[1] = fma2(cvt2(raw.y), one, acc2[1]);
            } else {
                unsigned raw = *(const unsigned*)(basep + k * (D * 2));
                acc2[0] = fma2(cvt2(raw), one, acc2[0]);
            }
        }
    }

    float inv = (d > 0) ? (1.0f / s) : (1.0f / NN);
    float accf[FPL];
#pragma unroll
    for (int q = 0; q < FPL / 2; q++) {
        float2 t = unpk(acc2[q]);
        accf[2 * q]     = t.x * inv;
        accf[2 * q + 1] = t.y * inv;
    }
#pragma unroll
    for (int q = 0; q < FPL; q++)
        accf[q] = (accf[q] > 0.0f) ? accf[q] : expm1f(accf[q]);

    float* op = out + (long)i * iStride + h * hStride + lane * FPL;
    if (FPL == 4) *(float4*)op = make_float4(accf[0], accf[1], accf[2], accf[3]);
    else          *(float2*)op = make_float2(accf[0], accf[1]);
}

// ---------------- launch ----------------
extern "C" void kernel_launch(void* const* d_in, const int* in_sizes, int n_in,
                              void* d_out, int out_size) {
    const float* x     = (const float*)d_in[0];
    const float* adj   = (const float*)d_in[1];
    const int*   obs   = (const int*)  d_in[2];
    // d_in[3] = s_mat (unused)
    const float* theta = (const float*)d_in[4];
    const float* W0    = (const float*)d_in[5];
    const float* a0    = (const float*)d_in[6];
    const float* W1    = (const float*)d_in[7];
    const float* a1    = (const float*)d_in[8];
    const float* Wo    = (const float*)d_in[9];
    const float* ao    = (const float*)d_in[10];
    float* out = (float*)d_out;

    void *pWhb, *pHa, *pHc, *pWhob, *pF1, *pF2, *pF1o, *pF2o;
    cudaGetSymbolAddress(&pWhb,  g_Whb);
    cudaGetSymbolAddress(&pHa,   g_ha);
    cudaGetSymbolAddress(&pHc,   g_hc);
    cudaGetSymbolAddress(&pWhob, g_Whob);
    cudaGetSymbolAddress(&pF1,   g_f1);
    cudaGetSymbolAddress(&pF2,   g_f2);
    cudaGetSymbolAddress(&pF1o,  g_f1o);
    cudaGetSymbolAddress(&pF2o,  g_f2o);

    thetaW_kernel<<<HH, DD>>>(theta, W0);
    build_csr_kernel<<<NN, 256>>>(adj);

    // ---- layer 0 (theta merged in epilogue) ----
    mma_gemm<64, 128, 16, 32, 64, true><<<dim3(1, NN / 64, HH), 128>>>(
        x, W0, (__nv_bfloat16*)pWhb, a0,
        (float*)pF1, (float*)pF2, NN, DD, FF,
        0L, (long)FF * DD, 2L * DD, obs);
    attn_warp<DD><<<dim3(NN / 8, HH), 256>>>((const __nv_bfloat16*)pWhb,
                                             (const float*)pF1, (const float*)pF2,
                                             (float*)pHa, DD, NN * DD);

    // ---- layer 1 (output written directly in concat layout) ----
    mma_gemm<64, 128, 16, 32, 64, false><<<dim3(1, NN / 64, HH), 128>>>(
        (const float*)pHa, W1, (__nv_bfloat16*)pWhb, a1,
        (float*)pF1, (float*)pF2, NN, DD, DD,
        (long)NN * DD, (long)DD * DD, 2L * DD, nullptr);
    attn_warp<DD><<<dim3(NN / 8, HH), 256>>>((const __nv_bfloat16*)pWhb,
                                             (const float*)pF1, (const float*)pF2,
                                             (float*)pHc, HH * DD, DD);

    // ---- output layer: split-K GEMM + combine ----
    mma_splitk<<<dim3(SPLITK, NN / 64), 128>>>(
        (const float*)pHc, Wo, NN, OUTD, HH * DD);
    out_epi<<<NN / 8, 256>>>(ao);
    attn_warp<OUTD><<<dim3(NN / 8, 1), 256>>>((const __nv_bfloat16*)pWhob,
                                              (const float*)pF1o, (const float*)pF2o,
                                              out, OUTD, 0);
    (void)in_sizes; (void)n_in; (void)out_size;
}

// round 13
// speedup vs baseline: 1.1168x; 1.0530x over previous
#include <cuda_runtime.h>
#include <cuda_bf16.h>

// Problem constants
#define NN   3072
#define FF   256
#define HH   8
#define DD   128
#define OUTD 64
#define MAXD 384
#define SPLITK 4

// ---------------- device scratch ----------------
__device__ __align__(16) __nv_bfloat16 g_Whb [HH * NN * DD];
__device__ __align__(16) float         g_ha  [HH * NN * DD];
__device__ __align__(16) float         g_hc  [NN * HH * DD];
__device__ __align__(16) float         g_who [SPLITK * NN * OUTD];
__device__ __align__(16) __nv_bfloat16 g_Whob[NN * OUTD];
__device__ __align__(16) float         g_tw  [HH * DD];       // theta @ W0 per head
__device__ float g_f1 [HH * NN];
__device__ float g_f2 [HH * NN];
__device__ float g_f1o[NN];
__device__ float g_f2o[NN];
__device__ int   g_nbr[NN * MAXD];
__device__ int   g_deg[NN];

// ---------------- theta @ W0 precompute (per head) ----------------
__global__ void thetaW_kernel(const float* __restrict__ theta,
                              const float* __restrict__ W0) {
    int h = blockIdx.x;
    int c = threadIdx.x;            // 0..DD-1
    float s = 0.0f;
    const float* Wh = W0 + (long)h * FF * DD + c;
#pragma unroll 4
    for (int k = 0; k < FF; k++) s += theta[k] * Wh[(long)k * DD];
    g_tw[h * DD + c] = s;
}

// ---------------- CSR build (float4) ----------------
__global__ void build_csr_kernel(const float* __restrict__ adj) {
    int i = blockIdx.x;
    __shared__ int cnt;
    if (threadIdx.x == 0) cnt = 0;
    __syncthreads();
    const float4* row = (const float4*)(adj + (long)i * NN);
    for (int q = threadIdx.x; q < NN / 4; q += blockDim.x) {
        float4 v = row[q];
        int j = 4 * q;
        if (v.x > 0.0f) { int p = atomicAdd(&cnt, 1); if (p < MAXD) g_nbr[i * MAXD + p] = j; }
        if (v.y > 0.0f) { int p = atomicAdd(&cnt, 1); if (p < MAXD) g_nbr[i * MAXD + p] = j + 1; }
        if (v.z > 0.0f) { int p = atomicAdd(&cnt, 1); if (p < MAXD) g_nbr[i * MAXD + p] = j + 2; }
        if (v.w > 0.0f) { int p = atomicAdd(&cnt, 1); if (p < MAXD) g_nbr[i * MAXD + p] = j + 3; }
    }
    __syncthreads();
    if (threadIdx.x == 0) g_deg[i] = cnt < MAXD ? cnt : MAXD;
}

// ---------------- mma / cp.async helpers ----------------
__device__ __forceinline__ unsigned f2tf(unsigned bits) {
    unsigned u;
    asm("cvt.rna.tf32.f32 %0, %1;" : "=r"(u) : "r"(bits));
    return u;
}
__device__ __forceinline__ void mma_tf32(float c[4], const unsigned a[4], const unsigned b[2]) {
    asm("mma.sync.aligned.m16n8k8.row.col.f32.tf32.tf32.f32 "
        "{%0,%1,%2,%3}, {%4,%5,%6,%7}, {%8,%9}, {%0,%1,%2,%3};"
        : "+f"(c[0]), "+f"(c[1]), "+f"(c[2]), "+f"(c[3])
        : "r"(a[0]), "r"(a[1]), "r"(a[2]), "r"(a[3]), "r"(b[0]), "r"(b[1]));
}
__device__ __forceinline__ void cpa16(void* smem_dst, const void* gsrc) {
    unsigned saddr = (unsigned)__cvta_generic_to_shared(smem_dst);
    asm volatile("cp.async.ca.shared.global [%0], [%1], 16;" :: "r"(saddr), "l"(gsrc));
}
__device__ __forceinline__ void cpa_commit() { asm volatile("cp.async.commit_group;"); }
template <int N>
__device__ __forceinline__ void cpa_wait() { asm volatile("cp.async.wait_group %0;" :: "n"(N)); }

// bf16x2 word -> 2 floats (exact)
__device__ __forceinline__ float2 bf2f(unsigned u) {
    float2 r;
    r.x = __int_as_float(u << 16);
    r.y = __int_as_float(u & 0xffff0000u);
    return r;
}

// ---------------- 3-stage pipelined tf32 GEMM + fused epilogue ----------------
template <int BM, int BN, int BK, int WM, int WN, bool FUSE_THETA>
__global__ void mma_gemm(const float* __restrict__ A,
                         const float* __restrict__ B,
                         __nv_bfloat16* __restrict__ Cb,
                         const float* __restrict__ avec,
                         float* __restrict__ f1,
                         float* __restrict__ f2,
                         int M, int Nc, int K,
                         long strideA, long strideB, long strideAv,
                         const int* __restrict__ obs) {
    constexpr int WARPS_N = BN / WN;
    constexpr int WARPS_M = BM / WM;
    constexpr int THREADS = WARPS_M * WARPS_N * 32;
    constexpr int MT = WM / 16, NT = WN / 8;
    constexpr int AP = BK + 4;
    constexpr int BP = BN + 8;
    constexpr int A_OPS = BM * BK / (4 * THREADS);
    constexpr int B_OPS = BK * BN / (4 * THREADS);
    constexpr int ST = 3;

    __shared__ unsigned As[ST][BM][AP];
    __shared__ unsigned Bs[ST][BK][BP];
    __shared__ float f1s[BM], f2s[BM];

    int z = blockIdx.z;
    A    += (long)z * strideA;
    B    += (long)z * strideB;
    avec += (long)z * strideAv;
    Cb   += (long)z * M * Nc;
    f1   += (long)z * M;
    f2   += (long)z * M;

    int tid  = threadIdx.x;
    int brow = blockIdx.y * BM;
    int warp = tid >> 5, lane = tid & 31;
    int gid  = lane >> 2, tig = lane & 3;
    int wm   = (warp / WARPS_N) * WM;
    int wn   = (warp % WARPS_N) * WN;

    if (tid < BM) { f1s[tid] = 0.0f; f2s[tid] = 0.0f; }

    float c[MT][NT][4];
#pragma unroll
    for (int i = 0; i < MT; i++)
#pragma unroll
        for (int j = 0; j < NT; j++)
#pragma unroll
            for (int q = 0; q < 4; q++) c[i][j][q] = 0.0f;

    const int KT = K / BK;
    auto issue = [&](int kt, int s) {
        int k0 = kt * BK;
#pragma unroll
        for (int l = 0; l < A_OPS; l++) {
            int idx = tid + l * THREADS;
            int r  = idx / (BK / 4);
            int c4 = idx % (BK / 4);
            cpa16(&As[s][r][c4 * 4], &A[(long)(brow + r) * K + k0 + c4 * 4]);
        }
#pragma unroll
        for (int l = 0; l < B_OPS; l++) {
            int idx = tid + l * THREADS;
            int r  = idx / (BN / 4);
            int c4 = idx % (BN / 4);
            cpa16(&Bs[s][r][c4 * 4], &B[(long)(k0 + r) * Nc + c4 * 4]);
        }
        cpa_commit();
    };
    auto compute = [&](int s) {
#pragma unroll
        for (int kk = 0; kk < BK; kk += 8) {
            unsigned a[MT][4], b[NT][2];
#pragma unroll
            for (int mt = 0; mt < MT; mt++) {
                int r0 = wm + mt * 16 + gid;
                a[mt][0] = f2tf(As[s][r0][kk + tig]);
                a[mt][1] = f2tf(As[s][r0 + 8][kk + tig]);
                a[mt][2] = f2tf(As[s][r0][kk + tig + 4]);
                a[mt][3] = f2tf(As[s][r0 + 8][kk + tig + 4]);
            }
#pragma unroll
            for (int nt = 0; nt < NT; nt++) {
                int cn = wn + nt * 8 + gid;
                b[nt][0] = f2tf(Bs[s][kk + tig][cn]);
                b[nt][1] = f2tf(Bs[s][kk + tig + 4][cn]);
            }
#pragma unroll
            for (int mt = 0; mt < MT; mt++)
#pragma unroll
                for (int nt = 0; nt < NT; nt++)
                    mma_tf32(c[mt][nt], a[mt], b[nt]);
        }
    };

    issue(0, 0);
    if (KT > 1) issue(1, 1);
    for (int kt = 0; kt < KT; kt++) {
        if (kt == KT - 1) cpa_wait<0>(); else cpa_wait<1>();
        __syncthreads();
        if (kt + 2 < KT) issue(kt + 2, (kt + 2) % ST);
        compute(kt % ST);
        __syncthreads();
    }

    // ---- epilogue: (+theta) bf16 store + f1/f2 ----
#pragma unroll
    for (int mt = 0; mt < MT; mt++) {
        int rl0 = wm + mt * 16 + gid;
        int rl1 = rl0 + 8;
        bool s0 = false, s1 = false;
        if (FUSE_THETA) {
            s0 = (obs[brow + rl0] == 1);
            s1 = (obs[brow + rl1] == 1);
        }
        float p10 = 0.f, p20 = 0.f, p11 = 0.f, p21 = 0.f;
#pragma unroll
        for (int nt = 0; nt < NT; nt++) {
            int col = wn + nt * 8 + tig * 2;
            float c0 = c[mt][nt][0], c1 = c[mt][nt][1];
            float c2 = c[mt][nt][2], c3 = c[mt][nt][3];
            if (FUSE_THETA) {
                float tw0 = g_tw[z * DD + col], tw1 = g_tw[z * DD + col + 1];
                if (s0) { c0 += tw0; c1 += tw1; }
                if (s1) { c2 += tw0; c3 += tw1; }
            }
            float a0 = __ldg(&avec[col]),      a1 = __ldg(&avec[col + 1]);
            float b0 = __ldg(&avec[Nc + col]), b1 = __ldg(&avec[Nc + col + 1]);
            p10 += c0 * a0 + c1 * a1;
            p20 += c0 * b0 + c1 * b1;
            p11 += c2 * a0 + c3 * a1;
            p21 += c2 * b0 + c3 * b1;
            *(__nv_bfloat162*)&Cb[(long)(brow + rl0) * Nc + col] =
                __float22bfloat162_rn(make_float2(c0, c1));
            *(__nv_bfloat162*)&Cb[(long)(brow + rl1) * Nc + col] =
                __float22bfloat162_rn(make_float2(c2, c3));
        }
#pragma unroll
        for (int o = 2; o; o >>= 1) {
            p10 += __shfl_down_sync(0xffffffffu, p10, o, 4);
            p20 += __shfl_down_sync(0xffffffffu, p20, o, 4);
            p11 += __shfl_down_sync(0xffffffffu, p11, o, 4);
            p21 += __shfl_down_sync(0xffffffffu, p21, o, 4);
        }
        if (tig == 0) {
            atomicAdd(&f1s[rl0], p10);
            atomicAdd(&f2s[rl0], p20);
            atomicAdd(&f1s[rl1], p11);
            atomicAdd(&f2s[rl1], p21);
        }
    }
    __syncthreads();
    if (tid < BM) {
        f1[brow + tid] = f1s[tid];
        f2[brow + tid] = f2s[tid];
    }
}

// ---------------- split-K output GEMM (fp32 partials, no atomics) ----------------
__global__ void mma_splitk(const float* __restrict__ A,
                           const float* __restrict__ B,
                           int M, int Nc, int K) {
    constexpr int BM = 64, BN = 64, BK = 16;
    constexpr int THREADS = 128;
    constexpr int MT = 2, NT = 4;
    constexpr int AP = BK + 4;
    constexpr int BP = BN + 8;
    constexpr int A_OPS = BM * BK / (4 * THREADS);
    constexpr int B_OPS = BK * BN / (4 * THREADS);
    constexpr int ST = 3;

    __shared__ unsigned As[ST][BM][AP];
    __shared__ unsigned Bs[ST][BK][BP];

    int tid  = threadIdx.x;
    int ksp  = blockIdx.x;
    int brow = blockIdx.y * BM;
    int kBeg = ksp * (K / SPLITK);
    int warp = tid >> 5, lane = tid & 31;
    int gid  = lane >> 2, tig = lane & 3;
    int wm   = (warp / 2) * 32;
    int wn   = (warp % 2) * 32;
    float* Cf = g_who + (long)ksp * M * Nc;

    float c[MT][NT][4];
#pragma unroll
    for (int i = 0; i < MT; i++)
#pragma unroll
        for (int j = 0; j < NT; j++)
#pragma unroll
            for (int q = 0; q < 4; q++) c[i][j][q] = 0.0f;

    const int KT = (K / SPLITK) / BK;
    auto issue = [&](int kt, int s) {
        int k0 = kBeg + kt * BK;
#pragma unroll
        for (int l = 0; l < A_OPS; l++) {
            int idx = tid + l * THREADS;
            int r  = idx / (BK / 4);
            int c4 = idx % (BK / 4);
            cpa16(&As[s][r][c4 * 4], &A[(long)(brow + r) * K + k0 + c4 * 4]);
        }
#pragma unroll
        for (int l = 0; l < B_OPS; l++) {
            int idx = tid + l * THREADS;
            int r  = idx / (BN / 4);
            int c4 = idx % (BN / 4);
            cpa16(&Bs[s][r][c4 * 4], &B[(long)(k0 + r) * Nc + c4 * 4]);
        }
        cpa_commit();
    };
    auto compute = [&](int s) {
#pragma unroll
        for (int kk = 0; kk < BK; kk += 8) {
            unsigned a[MT][4], b[NT][2];
#pragma unroll
            for (int mt = 0; mt < MT; mt++) {
                int r0 = wm + mt * 16 + gid;
                a[mt][0] = f2tf(As[s][r0][kk + tig]);
                a[mt][1] = f2tf(As[s][r0 + 8][kk + tig]);
                a[mt][2] = f2tf(As[s][r0][kk + tig + 4]);
                a[mt][3] = f2tf(As[s][r0 + 8][kk + tig + 4]);
            }
#pragma unroll
            for (int nt = 0; nt < NT; nt++) {
                int cn = wn + nt * 8 + gid;
                b[nt][0] = f2tf(Bs[s][kk + tig][cn]);
                b[nt][1] = f2tf(Bs[s][kk + tig + 4][cn]);
            }
#pragma unroll
            for (int mt = 0; mt < MT; mt++)
#pragma unroll
                for (int nt = 0; nt < NT; nt++)
                    mma_tf32(c[mt][nt], a[mt], b[nt]);
        }
    };

    issue(0, 0);
    if (KT > 1) issue(1, 1);
    for (int kt = 0; kt < KT; kt++) {
        if (kt == KT - 1) cpa_wait<0>(); else cpa_wait<1>();
        __syncthreads();
        if (kt + 2 < KT) issue(kt + 2, (kt + 2) % ST);
        compute(kt % ST);
        __syncthreads();
    }

#pragma unroll
    for (int mt = 0; mt < MT; mt++) {
        int rl0 = brow + wm + mt * 16 + gid;
        int rl1 = rl0 + 8;
#pragma unroll
        for (int nt = 0; nt < NT; nt++) {
            int col = wn + nt * 8 + tig * 2;
            *(float2*)&Cf[(long)rl0 * Nc + col] = make_float2(c[mt][nt][0], c[mt][nt][1]);
            *(float2*)&Cf[(long)rl1 * Nc + col] = make_float2(c[mt][nt][2], c[mt][nt][3]);
        }
    }
}

// ---------------- combine split-K partials + f1o/f2o + bf16 ----------------
__global__ void out_epi(const float* __restrict__ ao) {
    int warp = threadIdx.x >> 5, lane = threadIdx.x & 31;
    int r = blockIdx.x * 8 + warp;
    float v0 = 0.f, v1 = 0.f;
#pragma unroll
    for (int s = 0; s < SPLITK; s++) {
        const float* row = g_who + (long)s * NN * OUTD + (long)r * OUTD;
        v0 += row[lane];
        v1 += row[lane + 32];
    }
    float p1 = v0 * __ldg(&ao[lane]) + v1 * __ldg(&ao[lane + 32]);
    float p2 = v0 * __ldg(&ao[OUTD + lane]) + v1 * __ldg(&ao[OUTD + lane + 32]);
#pragma unroll
    for (int o = 16; o; o >>= 1) {
        p1 += __shfl_xor_sync(0xffffffffu, p1, o);
        p2 += __shfl_xor_sync(0xffffffffu, p2, o);
    }
    if (lane == 0) { g_f1o[r] = p1; g_f2o[r] = p2; }
    g_Whob[r * OUTD + lane]      = __float2bfloat16(v0);
    g_Whob[r * OUTD + lane + 32] = __float2bfloat16(v1);
}

// ---------------- warp-per-(i,h) sparse attention + ELU (R7 shape, paired LDS) ----------------
// block = 256 (8 warps), grid = (NN/8, nHeads). 1 row per warp; 32 lanes span the row.
template <int D>
__global__ void attn_warp(const __nv_bfloat16* __restrict__ Whb,
                          const float* __restrict__ f1,
                          const float* __restrict__ f2,
                          float* __restrict__ out,
                          int iStride, int hStride) {
    constexpr int WPB = 8;
    constexpr int FPL = D / 32;          // floats per lane: 4 (D=128) or 2 (D=64)
    __shared__ __align__(16) float2 wns[WPB][MAXD];
    int warp = threadIdx.x >> 5, lane = threadIdx.x & 31;
    int i = blockIdx.x * WPB + warp;
    int h = blockIdx.y;
    const __nv_bfloat16* WhH = Whb + h * (NN * D);
    const float* f2H = f2 + h * NN;
    float f1i = f1[h * NN + i];
    int d = g_deg[i];
    float2* w = wns[warp];
    const unsigned FULL = 0xffffffffu;

    // pass A: e = leakyrelu(f1_i + f2_j), track max
    float m = -3.4e38f;
    for (int k = lane; k < d; k += 32) {
        int j = g_nbr[i * MAXD + k];
        float e = f1i + f2H[j];
        e = (e > 0.0f) ? e : 0.2f * e;
        m = fmaxf(m, e);
        w[k] = make_float2(e, __int_as_float(j * (D * 2)));
    }
#pragma unroll
    for (int o = 16; o; o >>= 1) m = fmaxf(m, __shfl_xor_sync(FULL, m, o));

    // pass B: exp + sum
    float s = 0.0f;
    for (int k = lane; k < d; k += 32) {
        float v = __expf(w[k].x - m);
        w[k].x = v;
        s += v;
    }
#pragma unroll
    for (int o = 16; o; o >>= 1) s += __shfl_xor_sync(FULL, s, o);
    __syncwarp();

    // pass C: gather — all 32 lanes per neighbor, FPL feats/lane.
    // Paired weight-table read: one LDS.128 covers 2 neighbors' {w, off}.
    const char* basep = (const char*)WhH + lane * (FPL * 2);
    float acc[FPL];
#pragma unroll
    for (int q = 0; q < FPL; q++) acc[q] = 0.0f;

    if (d > 0) {
        int k = 0;
#pragma unroll 4
        for (; k + 1 < d; k += 2) {
            float4 pp = *(const float4*)&w[k];   // {w0, off0, w1, off1}
            int off0 = __float_as_int(pp.y);
            int off1 = __float_as_int(pp.w);
            if (FPL == 4) {
                uint2 r0 = *(const uint2*)(basep + off0);
                uint2 r1 = *(const uint2*)(basep + off1);
                float2 a0 = bf2f(r0.x), a1 = bf2f(r0.y);
                float2 b0 = bf2f(r1.x), b1 = bf2f(r1.y);
                acc[0] += pp.x * a0.x; acc[1] += pp.x * a0.y;
                acc[2] += pp.x * a1.x; acc[3] += pp.x * a1.y;
                acc[0] += pp.z * b0.x; acc[1] += pp.z * b0.y;
                acc[2] += pp.z * b1.x; acc[3] += pp.z * b1.y;
            } else {
                unsigned r0 = *(const unsigned*)(basep + off0);
                unsigned r1 = *(const unsigned*)(basep + off1);
                float2 a0 = bf2f(r0), b0 = bf2f(r1);
                acc[0] += pp.x * a0.x; acc[1] += pp.x * a0.y;
                acc[0] += pp.z * b0.x; acc[1] += pp.z * b0.y;
            }
        }
        if (k < d) {
            float2 p = w[k];
            float wk = p.x;
            int off = __float_as_int(p.y);
            if (FPL == 4) {
                uint2 raw = *(const uint2*)(basep + off);
                float2 c0 = bf2f(raw.x), c1 = bf2f(raw.y);
                acc[0] += wk * c0.x; acc[1] += wk * c0.y;
                acc[2] += wk * c1.x; acc[3] += wk * c1.y;
            } else {
                unsigned raw = *(const unsigned*)(basep + off);
                float2 c0 = bf2f(raw);
                acc[0] += wk * c0.x; acc[1] += wk * c0.y;
            }
        }
        float inv = 1.0f / s;
#pragma unroll
        for (int q = 0; q < FPL; q++) acc[q] *= inv;
    } else {
        // uniform attention over all nodes (softmax of constant row)
        for (int k = 0; k < NN; k++) {
            if (FPL == 4) {
                uint2 raw = *(const uint2*)(basep + k * (D * 2));
                float2 c0 = bf2f(raw.x), c1 = bf2f(raw.y);
                acc[0] += c0.x; acc[1] += c0.y; acc[2] += c1.x; acc[3] += c1.y;
            } else {
                unsigned raw = *(const unsigned*)(basep + k * (D * 2));
                float2 c0 = bf2f(raw);
                acc[0] += c0.x; acc[1] += c0.y;
            }
        }
#pragma unroll
        for (int q = 0; q < FPL; q++) acc[q] *= (1.0f / NN);
    }

    // ELU + coalesced store
    float* op = out + (long)i * iStride + h * hStride + lane * FPL;
#pragma unroll
    for (int q = 0; q < FPL; q++) acc[q] = (acc[q] > 0.0f) ? acc[q] : expm1f(acc[q]);
    if (FPL == 4) *(float4*)op = make_float4(acc[0], acc[1], acc[2], acc[3]);
    else          *(float2*)op = make_float2(acc[0], acc[1]);
}

// ---------------- launch ----------------
extern "C" void kernel_launch(void* const* d_in, const int* in_sizes, int n_in,
                              void* d_out, int out_size) {
    const float* x     = (const float*)d_in[0];
    const float* adj   = (const float*)d_in[1];
    const int*   obs   = (const int*)  d_in[2];
    // d_in[3] = s_mat (unused)
    const float* theta = (const float*)d_in[4];
    const float* W0    = (const float*)d_in[5];
    const float* a0    = (const float*)d_in[6];
    const float* W1    = (const float*)d_in[7];
    const float* a1    = (const float*)d_in[8];
    const float* Wo    = (const float*)d_in[9];
    const float* ao    = (const float*)d_in[10];
    float* out = (float*)d_out;

    void *pWhb, *pHa, *pHc, *pWhob, *pF1, *pF2, *pF1o, *pF2o;
    cudaGetSymbolAddress(&pWhb,  g_Whb);
    cudaGetSymbolAddress(&pHa,   g_ha);
    cudaGetSymbolAddress(&pHc,   g_hc);
    cudaGetSymbolAddress(&pWhob, g_Whob);
    cudaGetSymbolAddress(&pF1,   g_f1);
    cudaGetSymbolAddress(&pF2,   g_f2);
    cudaGetSymbolAddress(&pF1o,  g_f1o);
    cudaGetSymbolAddress(&pF2o,  g_f2o);

    thetaW_kernel<<<HH, DD>>>(theta, W0);
    build_csr_kernel<<<NN, 256>>>(adj);

    // ---- layer 0 (theta merged in epilogue) ----
    mma_gemm<64, 128, 16, 32, 64, true><<<dim3(1, NN / 64, HH), 128>>>(
        x, W0, (__nv_bfloat16*)pWhb, a0,
        (float*)pF1, (float*)pF2, NN, DD, FF,
        0L, (long)FF * DD, 2L * DD, obs);
    attn_warp<DD><<<dim3(NN / 8, HH), 256>>>((const __nv_bfloat16*)pWhb,
                                             (const float*)pF1, (const float*)pF2,
                                             (float*)pHa, DD, NN * DD);

    // ---- layer 1 (output written directly in concat layout) ----
    mma_gemm<64, 128, 16, 32, 64, false><<<dim3(1, NN / 64, HH), 128>>>(
        (const float*)pHa, W1, (__nv_bfloat16*)pWhb, a1,
        (float*)pF1, (float*)pF2, NN, DD, DD,
        (long)NN * DD, (long)DD * DD, 2L * DD, nullptr);
    attn_warp<DD><<<dim3(NN / 8, HH), 256>>>((const __nv_bfloat16*)pWhb,
                                             (const float*)pF1, (const float*)pF2,
                                             (float*)pHc, HH * DD, DD);

    // ---- output layer: split-K GEMM + combine ----
    mma_splitk<<<dim3(SPLITK, NN / 64), 128>>>(
        (const float*)pHc, Wo, NN, OUTD, HH * DD);
    out_epi<<<NN / 8, 256>>>(ao);
    attn_warp<OUTD><<<dim3(NN / 8, 1), 256>>>((const __nv_bfloat16*)pWhob,
                                              (const float*)pF1o, (const float*)pF2o,
                                              out, OUTD, 0);
    (void)in_sizes; (void)n_in; (void)out_size;
}